// round 1
// baseline (speedup 1.0000x reference)
#include <cuda_runtime.h>
#include <cstdint>

#define VOCAB 50000
#define EMB   32
#define HID   64
#define H4    256
#define NCLS  3
#define BSZ   512
#define TLEN  512

// 51.2MB scratch: precomputed emb @ Wk + bias, per vocab entry (256 floats each)
__device__ float g_table[(size_t)VOCAB * H4];

// ---------- packed f32x2 helpers (sm_103a FFMA2 path, PTX-only) ----------
__device__ __forceinline__ unsigned long long pack2(float lo, float hi) {
    unsigned long long r;
    asm("mov.b64 %0, {%1, %2};" : "=l"(r) : "f"(lo), "f"(hi));
    return r;
}
__device__ __forceinline__ float2 unpack2(unsigned long long v) {
    float2 f;
    asm("mov.b64 {%0, %1}, %2;" : "=f"(f.x), "=f"(f.y) : "l"(v));
    return f;
}
#define FMA2(acc, a, b) \
    asm("fma.rn.f32x2 %0, %1, %2, %0;" : "+l"(acc) : "l"(a), "l"(b))

__device__ __forceinline__ float sigf(float x) {
    // 1/(1+e^-x); handles +/-inf saturation correctly in fp32
    float t = __expf(-x);
    return 1.0f / (1.0f + t);
}
__device__ __forceinline__ float tanh_acc(float x) {
    // tanh via exp of negative magnitude (no overflow), ~2ulp
    float a  = fabsf(x);
    float t  = __expf(-2.0f * a);
    float r  = (1.0f - t) / (1.0f + t);
    return copysignf(r, x);
}

// ---------- kernel 1: g_table[v][j] = sum_e emb[v][e]*Wk[e][j] + b[j] ----------
__global__ __launch_bounds__(256) void table_kernel(
    const float* __restrict__ emb, const float* __restrict__ Wk,
    const float* __restrict__ bias)
{
    __shared__ __align__(16) float sh_e[64 * EMB];  // 64 vocab rows staged
    const int j  = threadIdx.x;                     // output column 0..255
    const int v0 = blockIdx.x * 64;

    // Wk column j, packed in pairs over e: 16 b64 regs
    unsigned long long wk2[16];
#pragma unroll
    for (int m = 0; m < 16; m++)
        wk2[m] = pack2(Wk[(2 * m) * H4 + j], Wk[(2 * m + 1) * H4 + j]);
    const float bj = bias[j];

    const int nrows = min(64, VOCAB - v0);
    // stage emb rows (contiguous), vectorized
    const float4* src = reinterpret_cast<const float4*>(emb + (size_t)v0 * EMB);
    float4* dst = reinterpret_cast<float4*>(sh_e);
    for (int i = j; i < nrows * (EMB / 4); i += 256) dst[i] = src[i];
    __syncthreads();

    for (int r = 0; r < nrows; r++) {
        const ulonglong2* ev = reinterpret_cast<const ulonglong2*>(sh_e + r * EMB);
        unsigned long long a0 = 0ull, a1 = 0ull;
#pragma unroll
        for (int m = 0; m < 4; m++) {
            ulonglong2 p = ev[2 * m];
            ulonglong2 q = ev[2 * m + 1];
            FMA2(a0, p.x, wk2[4 * m + 0]);
            FMA2(a1, p.y, wk2[4 * m + 1]);
            FMA2(a0, q.x, wk2[4 * m + 2]);
            FMA2(a1, q.y, wk2[4 * m + 3]);
        }
        float2 f0 = unpack2(a0), f1 = unpack2(a1);
        g_table[(size_t)(v0 + r) * H4 + j] = bj + (f0.x + f0.y) + (f1.x + f1.y);
    }
}

// ---------- kernel 2: recurrent LSTM, 2 batch rows per CTA ----------
// Thread j owns gate-column j (0..255). Wr column j register-resident,
// packed in pairs over k (32 b64 regs). h broadcast via 128-bit shared loads.
__global__ __launch_bounds__(256, 2) void lstm_kernel(
    const int*   __restrict__ tokens,
    const float* __restrict__ Wr,
    const float* __restrict__ Wd,
    const float* __restrict__ bd,
    float*       __restrict__ out)
{
    __shared__ __align__(16) float sh_h[2][HID];
    __shared__ float sh_z[2][H4];
    __shared__ int   sh_tok[2][TLEN];

    const int j  = threadIdx.x;
    const int b0 = blockIdx.x * 2;

    // stage this CTA's token rows
    for (int i = j; i < 2 * TLEN; i += 256) {
        int s = i >> 9, t = i & (TLEN - 1);
        sh_tok[s][t] = tokens[(size_t)(b0 + s) * TLEN + t];
    }

    // Wr column j, packed over k: wr2[m] = (Wr[2m][j], Wr[2m+1][j])
    unsigned long long wr2[32];
#pragma unroll
    for (int m = 0; m < 32; m++)
        wr2[m] = pack2(Wr[(2 * m) * H4 + j], Wr[(2 * m + 1) * H4 + j]);

    if (j < 2 * HID) sh_h[j >> 6][j & (HID - 1)] = 0.0f;
    float cst = 0.0f;  // cell state for (s = j>>6, u = j&63), valid for j<128
    __syncthreads();

    // prefetch xz for t=0
    float xzn0 = g_table[(size_t)sh_tok[0][0] * H4 + j];
    float xzn1 = g_table[(size_t)sh_tok[1][0] * H4 + j];

#pragma unroll 1
    for (int t = 0; t < TLEN; t++) {
        const float xz0 = xzn0, xz1 = xzn1;
        // prefetch next step's gathered input projection (L2-resident table)
        const int tn = (t < TLEN - 1) ? t + 1 : t;
        const int tk0 = sh_tok[0][tn], tk1 = sh_tok[1][tn];
        xzn0 = g_table[(size_t)tk0 * H4 + j];
        xzn1 = g_table[(size_t)tk1 * H4 + j];

        // z[s][j] = xz + h[s] . Wr[:,j]   (packed f32x2, 4 chains per batch)
        const ulonglong2* h0 = reinterpret_cast<const ulonglong2*>(sh_h[0]);
        const ulonglong2* h1 = reinterpret_cast<const ulonglong2*>(sh_h[1]);
        unsigned long long a0 = 0ull, a1 = 0ull, a2 = 0ull, a3 = 0ull;
        unsigned long long c0 = 0ull, c1 = 0ull, c2 = 0ull, c3 = 0ull;
#pragma unroll
        for (int m = 0; m < 8; m++) {
            ulonglong2 p0 = h0[2 * m];
            ulonglong2 q0 = h0[2 * m + 1];
            ulonglong2 p1 = h1[2 * m];
            ulonglong2 q1 = h1[2 * m + 1];
            FMA2(a0, p0.x, wr2[4 * m + 0]);
            FMA2(a1, p0.y, wr2[4 * m + 1]);
            FMA2(a2, q0.x, wr2[4 * m + 2]);
            FMA2(a3, q0.y, wr2[4 * m + 3]);
            FMA2(c0, p1.x, wr2[4 * m + 0]);
            FMA2(c1, p1.y, wr2[4 * m + 1]);
            FMA2(c2, q1.x, wr2[4 * m + 2]);
            FMA2(c3, q1.y, wr2[4 * m + 3]);
        }
        {
            float2 f0 = unpack2(a0), f1 = unpack2(a1), f2 = unpack2(a2), f3 = unpack2(a3);
            sh_z[0][j] = xz0 + ((f0.x + f0.y) + (f1.x + f1.y)) + ((f2.x + f2.y) + (f3.x + f3.y));
            float2 g0 = unpack2(c0), g1 = unpack2(c1), g2 = unpack2(c2), g3 = unpack2(c3);
            sh_z[1][j] = xz1 + ((g0.x + g0.y) + (g1.x + g1.y)) + ((g2.x + g2.y) + (g3.x + g3.y));
        }
        __syncthreads();

        if (j < 2 * HID) {
            const int s = j >> 6, u = j & (HID - 1);
            const float zi = sh_z[s][u];
            const float zf = sh_z[s][u + HID];
            const float zg = sh_z[s][u + 2 * HID];
            const float zo = sh_z[s][u + 3 * HID];
            const float ig = sigf(zi);
            const float fg = sigf(zf);
            const float og = sigf(zo);
            const float gg = tanh_acc(zg);
            cst = fg * cst + ig * gg;
            sh_h[s][u] = og * tanh_acc(cst);
        }
        __syncthreads();
    }

    // epilogue: dense(3) + softmax for the CTA's two batch rows
    if (j < 2) {
        const int s = j;
        float l0 = bd[0], l1 = bd[1], l2 = bd[2];
#pragma unroll 8
        for (int u = 0; u < HID; u++) {
            const float h = sh_h[s][u];
            l0 += h * Wd[u * NCLS + 0];
            l1 += h * Wd[u * NCLS + 1];
            l2 += h * Wd[u * NCLS + 2];
        }
        const float m  = fmaxf(l0, fmaxf(l1, l2));
        const float e0 = __expf(l0 - m);
        const float e1 = __expf(l1 - m);
        const float e2 = __expf(l2 - m);
        const float inv = 1.0f / (e0 + e1 + e2);
        float* o = out + (size_t)(b0 + s) * NCLS;
        o[0] = e0 * inv;
        o[1] = e1 * inv;
        o[2] = e2 * inv;
    }
}

extern "C" void kernel_launch(void* const* d_in, const int* in_sizes, int n_in,
                              void* d_out, int out_size)
{
    const int*   tokens = (const int*)  d_in[0];
    const float* emb    = (const float*)d_in[1];
    const float* Wk     = (const float*)d_in[2];
    const float* Wr     = (const float*)d_in[3];
    const float* b      = (const float*)d_in[4];
    const float* Wd     = (const float*)d_in[5];
    const float* bd     = (const float*)d_in[6];
    float* out = (float*)d_out;

    table_kernel<<<(VOCAB + 63) / 64, 256>>>(emb, Wk, b);
    lstm_kernel<<<BSZ / 2, 256>>>(tokens, Wr, Wd, bd, out);
}